// round 5
// baseline (speedup 1.0000x reference)
#include <cuda_runtime.h>
#include <math.h>

#define SOSID 2
#define EPSF  1e-6f

typedef unsigned long long u64;

// ---------------- persistent device state ----------------
__device__ float g_phi_hs[3200*512];   // tanh(enc @ Wh + bh), rows = b*100+l
__device__ float g_phi_fds[3200*512];  // tanh(field @ Wf + bf)
__device__ float g_zx[2080*2048];      // x_t @ lstm_W[0:512] + lstm_b, rows = t*32+b
__device__ float g_hbuf[2][32*512];
__device__ float g_cbuf[2][32*512];
__device__ float g_ot[32*512];
__device__ float g_gamma[32*512];
__device__ float g_alpha[32*512];
__device__ float g_ctx[32*512];
__device__ float g_att[32*512];
__device__ int          g_cnt;
__device__ volatile int g_gen;

// ---------------- f32x2 helpers ----------------
__device__ __forceinline__ u64 pk2(float lo, float hi){
    u64 r; asm("mov.b64 %0, {%1,%2};" : "=l"(r) : "f"(lo), "f"(hi)); return r;
}
__device__ __forceinline__ void upk2(u64 v, float& lo, float& hi){
    asm("mov.b64 {%0,%1}, %2;" : "=f"(lo), "=f"(hi) : "l"(v));
}
__device__ __forceinline__ u64 ffma2(u64 a, u64 b, u64 c){
    u64 r; asm("fma.rn.f32x2 %0, %1, %2, %3;" : "=l"(r) : "l"(a), "l"(b), "l"(c)); return r;
}
__device__ __forceinline__ u64 fadd2(u64 a, u64 b){
    u64 r; asm("add.rn.f32x2 %0, %1, %2;" : "=l"(r) : "l"(a), "l"(b)); return r;
}
__device__ __forceinline__ float sigf(float x){ return 1.f/(1.f+expf(-x)); }

// ---------------- software grid barrier (all 128 co-resident blocks) ----------
__device__ __forceinline__ void gsync(){
    __threadfence();
    __syncthreads();
    if (threadIdx.x == 0){
        int g = g_gen;
        if (atomicAdd(&g_cnt, 1) == (int)gridDim.x - 1){
            g_cnt = 0;
            __threadfence();
            g_gen = g + 1;
        } else {
            while (g_gen == g) { }
        }
    }
    __syncthreads();
}

// ================= precompute GEMM (from passing R3 kernel) ==================
// C[32 x cols] = A[32 x K] @ W[K x cols] (+ epilogue). Only EPI 0/1/2 used now.
template<int K, int NT, int KS, int AMODE, int GATED, int EPI>
__global__ void __launch_bounds__(2*(NT/4)*KS)
g32(const float* __restrict__ W, const float* __restrict__ Bv,
    const float* __restrict__ A, int lda,
    float* __restrict__ out,
    int ldw, int t, const int* __restrict__ lens,
    const float* __restrict__ p0, const float* __restrict__ p1)
{
    constexpr int CG  = NT/4;
    constexpr int TH  = 2*CG*KS;
    constexpr int ATS = 36;
    extern __shared__ float sm[];
    float* at = sm;
    u64*  red = (u64*)(sm + K*ATS);

    const int tid = threadIdx.x;
    const int cg  = tid % CG;
    const int rh  = (tid / CG) & 1;
    const int ks  = tid / (2*CG);
    const int rowBase = (int)blockIdx.y*32;

    for (int idx = tid; idx < 32*K; idx += TH) {
        int m = idx / K, k = idx - m*K;
        float v;
        if (AMODE==0)      v = A[(size_t)(rowBase+m)*lda + k];
        else               { int tt = blockIdx.y;
                             v = (tt==0) ? A[SOSID*512 + k]
                                         : p1[((size_t)m*64 + (tt-1))*512 + k]; }
        at[k*ATS + m] = v;
    }
    __syncthreads();

    u64 acc[8][4];
    #pragma unroll
    for (int i=0;i<8;i++){ acc[i][0]=0; acc[i][1]=0; acc[i][2]=0; acc[i][3]=0; }

    const int k0 = ks*(K/KS);
    const float* wp = W + (size_t)k0*ldw + (size_t)blockIdx.x*NT + cg*4;
    const float* ap = at + k0*ATS + rh*16;

    #pragma unroll 4
    for (int kk=0; kk<K/KS; kk++) {
        float4 w4 = *(const float4*)wp;
        u64 b0=pk2(w4.x,w4.x), b1=pk2(w4.y,w4.y), b2=pk2(w4.z,w4.z), b3=pk2(w4.w,w4.w);
        wp += ldw;
        u64 aa[8];
        #pragma unroll
        for (int i=0;i<8;i++) aa[i] = ((const u64*)ap)[i];
        ap += ATS;
        #pragma unroll
        for (int m2=0;m2<8;m2++){
            acc[m2][0]=ffma2(aa[m2],b0,acc[m2][0]);
            acc[m2][1]=ffma2(aa[m2],b1,acc[m2][1]);
            acc[m2][2]=ffma2(aa[m2],b2,acc[m2][2]);
            acc[m2][3]=ffma2(aa[m2],b3,acc[m2][3]);
        }
    }

    if (KS>1) {
        u64* mr = red + (size_t)tid*33;
        #pragma unroll
        for (int m2=0;m2<8;m2++){
            mr[4*m2+0]=acc[m2][0]; mr[4*m2+1]=acc[m2][1];
            mr[4*m2+2]=acc[m2][2]; mr[4*m2+3]=acc[m2][3];
        }
        __syncthreads();
        for (int s=KS/2; s>=1; s>>=1){
            if (ks < s){
                const u64* pr = mr + (size_t)(s*2*CG)*33;
                #pragma unroll
                for (int m2=0;m2<8;m2++){
                    acc[m2][0]=fadd2(acc[m2][0],pr[4*m2+0]);
                    acc[m2][1]=fadd2(acc[m2][1],pr[4*m2+1]);
                    acc[m2][2]=fadd2(acc[m2][2],pr[4*m2+2]);
                    acc[m2][3]=fadd2(acc[m2][3],pr[4*m2+3]);
                }
                if (s>1){
                    #pragma unroll
                    for (int m2=0;m2<8;m2++){
                        mr[4*m2+0]=acc[m2][0]; mr[4*m2+1]=acc[m2][1];
                        mr[4*m2+2]=acc[m2][2]; mr[4*m2+3]=acc[m2][3];
                    }
                }
            }
            __syncthreads();
        }
    }
    if (ks) return;

    int c0 = blockIdx.x*NT + cg*4;
    #pragma unroll
    for (int m2=0;m2<8;m2++){
        float v0[4], v1[4];
        upk2(acc[m2][0],v0[0],v1[0]); upk2(acc[m2][1],v0[1],v1[1]);
        upk2(acc[m2][2],v0[2],v1[2]); upk2(acc[m2][3],v0[3],v1[3]);
        #pragma unroll
        for (int r=0;r<2;r++){
            int row = rowBase + rh*16 + 2*m2 + r;
            const float* vv = r ? v1 : v0;
            #pragma unroll
            for (int j=0;j<4;j++){
                int c = c0 + j;
                float x = vv[j] + Bv[c];
                if (EPI==0)      g_phi_hs [(size_t)row*512 +c] = tanhf(x);
                else if (EPI==1) g_phi_fds[(size_t)row*512 +c] = tanhf(x);
                else             g_zx     [(size_t)row*2048+c] = x;
            }
        }
    }
    (void)out; (void)lens; (void)p0; (void)t;
}

// ================= persistent decoder kernel =================================
// grid = 128 blocks x 256 threads, co-resident; software grid sync between phases.

__device__ __forceinline__ void lstm_part(
    float* sm, u64* red, const float* __restrict__ lWh,
    const int* __restrict__ lens, int t, int blk, int tid)
{
    const int pb = t & 1, cb = pb ^ 1;
    for (int idx = tid; idx < 32*512; idx += 256){
        int m = idx >> 9, k = idx & 511;
        sm[k*36 + m] = __ldcg(&g_hbuf[pb][m*512 + k]);
    }
    __syncthreads();

    const int cg = tid & 3;          // h-col within block (h = blk*4+cg)
    const int rh = (tid >> 2) & 1;   // row half
    const int ks = tid >> 3;         // 0..31 K-split (16 k each)

    u64 acc[8][4];
    #pragma unroll
    for (int i=0;i<8;i++){ acc[i][0]=0; acc[i][1]=0; acc[i][2]=0; acc[i][3]=0; }

    const float* wp = lWh + (size_t)(ks*16)*2048 + blk*4 + cg;
    const float* ap = sm + (ks*16)*36 + rh*16;
    #pragma unroll 4
    for (int kk=0; kk<16; kk++){
        float w0=wp[0], w1=wp[512], w2=wp[1024], w3=wp[1536];
        u64 b0=pk2(w0,w0), b1=pk2(w1,w1), b2=pk2(w2,w2), b3=pk2(w3,w3);
        wp += 2048;
        u64 aa[8];
        #pragma unroll
        for (int i=0;i<8;i++) aa[i] = ((const u64*)ap)[i];
        ap += 36;
        #pragma unroll
        for (int m2=0;m2<8;m2++){
            acc[m2][0]=ffma2(aa[m2],b0,acc[m2][0]);
            acc[m2][1]=ffma2(aa[m2],b1,acc[m2][1]);
            acc[m2][2]=ffma2(aa[m2],b2,acc[m2][2]);
            acc[m2][3]=ffma2(aa[m2],b3,acc[m2][3]);
        }
    }

    u64* mr = red + (size_t)tid*33;
    #pragma unroll
    for (int m2=0;m2<8;m2++){
        mr[4*m2+0]=acc[m2][0]; mr[4*m2+1]=acc[m2][1];
        mr[4*m2+2]=acc[m2][2]; mr[4*m2+3]=acc[m2][3];
    }
    __syncthreads();
    for (int s=16; s>=1; s>>=1){
        if (ks < s){
            const u64* pr = mr + (size_t)(s*8)*33;
            #pragma unroll
            for (int m2=0;m2<8;m2++){
                acc[m2][0]=fadd2(acc[m2][0],pr[4*m2+0]);
                acc[m2][1]=fadd2(acc[m2][1],pr[4*m2+1]);
                acc[m2][2]=fadd2(acc[m2][2],pr[4*m2+2]);
                acc[m2][3]=fadd2(acc[m2][3],pr[4*m2+3]);
            }
            if (s>1){
                #pragma unroll
                for (int m2=0;m2<8;m2++){
                    mr[4*m2+0]=acc[m2][0]; mr[4*m2+1]=acc[m2][1];
                    mr[4*m2+2]=acc[m2][2]; mr[4*m2+3]=acc[m2][3];
                }
            }
        }
        __syncthreads();
    }

    if (ks == 0){
        const int h = blk*4 + cg;
        #pragma unroll
        for (int m2=0;m2<8;m2++){
            float zi[2],zj[2],zf[2],zo[2];
            upk2(acc[m2][0],zi[0],zi[1]); upk2(acc[m2][1],zj[0],zj[1]);
            upk2(acc[m2][2],zf[0],zf[1]); upk2(acc[m2][3],zo[0],zo[1]);
            #pragma unroll
            for (int r=0;r<2;r++){
                int b = rh*16 + 2*m2 + r;
                const float* zxp = g_zx + ((size_t)(t*32+b))*2048 + h;
                float vi = zi[r] + zxp[0];
                float vj = zj[r] + zxp[512];
                float vf = zf[r] + zxp[1024];
                float vo = zo[r] + zxp[1536];
                float cp = __ldcg(&g_cbuf[pb][b*512+h]);
                float hp = __ldcg(&g_hbuf[pb][b*512+h]);
                float cn = sigf(vf+1.f)*cp + sigf(vi)*tanhf(vj);
                float hn = sigf(vo)*tanhf(cn);
                bool fin = (t>0) && (t-1 >= lens[b]);
                g_ot[b*512+h]       = fin ? 0.f : hn;
                g_hbuf[cb][b*512+h] = fin ? hp  : hn;
                g_cbuf[cb][b*512+h] = fin ? cp  : cn;
            }
        }
    }
    __syncthreads();
}

__device__ __forceinline__ void logits_part(
    float* sm, u64* red, const float* __restrict__ oW, const float* __restrict__ ob,
    const int* __restrict__ lens, float* __restrict__ out, int tt, int blk, int tid)
{
    for (int idx = tid; idx < 32*512; idx += 256){
        int m = idx >> 9, k = idx & 511;
        sm[k*36 + m] = __ldcg(&g_att[m*512 + k]);
    }
    __syncthreads();

    const int cg = tid & 63;
    const int rh = (tid >> 6) & 1;
    const int ks = tid >> 7;         // 0..1

    u64 acc[8][4];
    #pragma unroll
    for (int i=0;i<8;i++){ acc[i][0]=0; acc[i][1]=0; acc[i][2]=0; acc[i][3]=0; }

    const float* wp = oW + (size_t)(ks*256)*32000 + blk*256 + cg*4;
    const float* ap = sm + (ks*256)*36 + rh*16;
    #pragma unroll 4
    for (int kk=0; kk<256; kk++){
        float4 w4 = *(const float4*)wp;
        u64 b0=pk2(w4.x,w4.x), b1=pk2(w4.y,w4.y), b2=pk2(w4.z,w4.z), b3=pk2(w4.w,w4.w);
        wp += 32000;
        u64 aa[8];
        #pragma unroll
        for (int i=0;i<8;i++) aa[i] = ((const u64*)ap)[i];
        ap += 36;
        #pragma unroll
        for (int m2=0;m2<8;m2++){
            acc[m2][0]=ffma2(aa[m2],b0,acc[m2][0]);
            acc[m2][1]=ffma2(aa[m2],b1,acc[m2][1]);
            acc[m2][2]=ffma2(aa[m2],b2,acc[m2][2]);
            acc[m2][3]=ffma2(aa[m2],b3,acc[m2][3]);
        }
    }

    u64* mr = red + (size_t)tid*33;
    #pragma unroll
    for (int m2=0;m2<8;m2++){
        mr[4*m2+0]=acc[m2][0]; mr[4*m2+1]=acc[m2][1];
        mr[4*m2+2]=acc[m2][2]; mr[4*m2+3]=acc[m2][3];
    }
    __syncthreads();
    if (ks == 0){
        const u64* pr = mr + (size_t)128*33;
        #pragma unroll
        for (int m2=0;m2<8;m2++){
            acc[m2][0]=fadd2(acc[m2][0],pr[4*m2+0]);
            acc[m2][1]=fadd2(acc[m2][1],pr[4*m2+1]);
            acc[m2][2]=fadd2(acc[m2][2],pr[4*m2+2]);
            acc[m2][3]=fadd2(acc[m2][3],pr[4*m2+3]);
        }
        const int c0 = blk*256 + cg*4;
        #pragma unroll
        for (int m2=0;m2<8;m2++){
            float v0[4], v1[4];
            upk2(acc[m2][0],v0[0],v1[0]); upk2(acc[m2][1],v0[1],v1[1]);
            upk2(acc[m2][2],v0[2],v1[2]); upk2(acc[m2][3],v0[3],v1[3]);
            #pragma unroll
            for (int r=0;r<2;r++){
                int row = rh*16 + 2*m2 + r;
                bool fin = (tt>0) && (tt-1 >= lens[row]);
                const float* vv = r ? v1 : v0;
                float* op = out + (size_t)row*2080000 + (size_t)tt*32000 + c0;
                #pragma unroll
                for (int j=0;j<4;j++)
                    op[j] = fin ? 0.f : (vv[j] + ob[c0+j]);
            }
        }
    }
    __syncthreads();
}

// 8 output cols x 32 rows per block; A row-major (padded) in smem
template<int K, int PAD, int MASKED>
__device__ __forceinline__ void proj8(
    const float* __restrict__ W, const float* __restrict__ Bv,
    const float* a, int colbase, int tid,
    float* __restrict__ dst, const int* __restrict__ lens, int t)
{
    const int c = colbase + (tid & 7);
    const int m = tid >> 3;
    const float* ar = a + (size_t)m*PAD;
    const float* w  = W + c;
    u64 s2 = 0;
    #pragma unroll 4
    for (int k=0; k<K; k+=2){
        s2 = ffma2(*(const u64*)(ar + k),
                   pk2(w[(size_t)k*512], w[(size_t)(k+1)*512]), s2);
    }
    float s0,s1; upk2(s2,s0,s1);
    float v = tanhf(s0 + s1 + Bv[c]);
    if (MASKED){ bool fin = (t>0) && (t-1 >= lens[m]); v = fin ? 0.f : v; }
    dst[m*512 + c] = v;
}

__global__ void __launch_bounds__(256, 1)
decoder_loop(const float* __restrict__ lWh,
             const float* __restrict__ Ws, const float* __restrict__ bs,
             const float* __restrict__ Wr, const float* __restrict__ br,
             const float* __restrict__ Wo, const float* __restrict__ bo,
             const float* __restrict__ oW, const float* __restrict__ ob,
             const float* __restrict__ enc,
             const int* __restrict__ lens,
             float* __restrict__ out)
{
    extern __shared__ float sm[];
    u64* red = (u64*)(sm + 512*36);
    const int blk = blockIdx.x;
    const int tid = threadIdx.x;
    const int warp = tid >> 5, lane = tid & 31;

    for (int t = 0; t < 65; t++){
        // ---------- P1: LSTM(t) everywhere + logits(t-1) on blocks<125 ----------
        lstm_part(sm, red, lWh, lens, t, blk, tid);
        if (t > 0 && blk < 125)
            logits_part(sm, red, oW, ob, lens, out, t-1, blk, tid);
        gsync();

        // ---------- P2: gamma/alpha, col-sliced (128 blocks x 8 cols) ----------
        for (int idx = tid; idx < 32*512; idx += 256){
            int m = idx >> 9, k = idx & 511;
            sm[m*520 + k] = __ldcg(&g_ot[m*512 + k]);
        }
        __syncthreads();
        if (blk < 64) proj8<512,520,0>(Ws, bs, sm, blk*8,      tid, g_gamma, lens, t);
        else          proj8<512,520,0>(Wr, br, sm, (blk-64)*8, tid, g_alpha, lens, t);
        gsync();

        // ---------- P3: attention per batch (blocks 0..31) ----------
        if (blk < 32){
            const int b = blk;
            float* sg  = sm;          // 512
            float* sa  = sm + 512;    // 512
            float* sh_ = sm + 1024;   // 100
            float* sf_ = sm + 1124;   // 100
            float* sw_ = sm + 1224;   // 100
            float* aux = sm + 1324;   // [0]=sumh,[1]=sumf,[2]=wden

            for (int i = tid; i < 512; i += 256){
                sg[i] = __ldcg(&g_gamma[b*512+i]);
                sa[i] = __ldcg(&g_alpha[b*512+i]);
            }
            __syncthreads();

            for (int l = warp; l < 100; l += 8){
                const float* ph = g_phi_hs  + ((size_t)b*100 + l)*512;
                const float* pf = g_phi_fds + ((size_t)b*100 + l)*512;
                float s1=0.f, s2=0.f;
                for (int k=lane; k<512; k+=32){ s1 += ph[k]*sg[k]; s2 += pf[k]*sa[k]; }
                #pragma unroll
                for (int o=16;o;o>>=1){ s1 += __shfl_xor_sync(~0u,s1,o); s2 += __shfl_xor_sync(~0u,s2,o); }
                if (lane==0){ sh_[l]=s1; sf_[l]=s2; }
            }
            __syncthreads();

            if (warp < 2){
                float* s = warp ? sf_ : sh_;
                float mx = -1e30f;
                for (int l=lane;l<100;l+=32) mx = fmaxf(mx, s[l]);
                #pragma unroll
                for (int o=16;o;o>>=1) mx = fmaxf(mx, __shfl_xor_sync(~0u,mx,o));
                float sum = 0.f;
                for (int l=lane;l<100;l+=32){ float e = expf(s[l]-mx); s[l]=e; sum+=e; }
                #pragma unroll
                for (int o=16;o;o>>=1) sum += __shfl_xor_sync(~0u,sum,o);
                if (lane==0) aux[warp] = EPSF + sum;
            }
            __syncthreads();

            if (warp == 0){
                float d1 = aux[0], d2 = aux[1];
                float wsum = 0.f;
                for (int l=lane;l<100;l+=32){ float w = (sh_[l]/d1)*(sf_[l]/d2); sw_[l]=w; wsum += w; }
                #pragma unroll
                for (int o=16;o;o>>=1) wsum += __shfl_xor_sync(~0u,wsum,o);
                if (lane==0) aux[2] = EPSF + wsum;
            }
            __syncthreads();
            if (warp == 0){ float d = aux[2]; for (int l=lane;l<100;l+=32) sw_[l] = sw_[l]/d; }
            __syncthreads();

            #pragma unroll
            for (int ci=0; ci<2; ci++){
                int h = tid + ci*256;
                float c2 = 0.f;
                const float* e = enc + (size_t)b*100*512 + h;
                #pragma unroll 4
                for (int l=0;l<100;l++) c2 += sw_[l]*e[(size_t)l*512];
                g_ctx[b*512+h] = c2;
            }
        }
        gsync();

        // ---------- P4: att = tanh([ctx|ot] @ Wo + bo), 64 blocks x 8 cols ------
        if (blk < 64){
            for (int idx = tid; idx < 32*1024; idx += 256){
                int m = idx >> 10, k = idx & 1023;
                float v = (k < 512) ? __ldcg(&g_ctx[m*512+k]) : __ldcg(&g_ot[m*512+k-512]);
                sm[m*1032 + k] = v;
            }
            __syncthreads();
            proj8<1024,1032,1>(Wo, bo, sm, blk*8, tid, g_att, lens, t);
        }
        gsync();
    }

    // ---------- tail: logits(64) + final h/c ----------
    if (blk < 125)
        logits_part(sm, red, oW, ob, lens, out, 64, blk, tid);
    if (blk == 125)
        for (int i = tid; i < 16384; i += 256) out[66560000 + i] = __ldcg(&g_hbuf[1][i]);
    if (blk == 126)
        for (int i = tid; i < 16384; i += 256) out[66560000 + 16384 + i] = __ldcg(&g_cbuf[1][i]);
}

// ---------------- host ----------------
extern "C" void kernel_launch(void* const* d_in, const int* in_sizes, int n_in,
                              void* d_out, int out_size)
{
    const float* h0   = (const float*)d_in[0];
    const float* c0   = (const float*)d_in[1];
    const float* inp  = (const float*)d_in[2];   // (32,64,512)
    const float* enc  = (const float*)d_in[3];   // (32,100,512)
    const float* fld  = (const float*)d_in[4];   // (32,100,64)
    const float* emb  = (const float*)d_in[5];   // (32000,512)
    const float* lW   = (const float*)d_in[6];   // (1024,2048)
    const float* lb   = (const float*)d_in[7];
    const float* Wh   = (const float*)d_in[8];
    const float* bh   = (const float*)d_in[9];
    const float* Ws   = (const float*)d_in[10];
    const float* bs   = (const float*)d_in[11];
    const float* Wr   = (const float*)d_in[12];
    const float* br   = (const float*)d_in[13];
    const float* Wf   = (const float*)d_in[14];
    const float* bf   = (const float*)d_in[15];
    const float* Wo   = (const float*)d_in[16];
    const float* bo   = (const float*)d_in[17];
    const float* oW   = (const float*)d_in[18];
    const float* ob   = (const float*)d_in[19];
    const int*   lens = (const int*)  d_in[20];
    float* out = (float*)d_out;

    const int SM512_256 = 512*36*4 + 256*33*8;   // 141312
    const int SM64_256  = 64*36*4  + 256*33*8;   //  76800
    const int SM_PERS   = 141312;

    cudaFuncSetAttribute((const void*)g32<512,256,2,0,0,0>, cudaFuncAttributeMaxDynamicSharedMemorySize, SM512_256);
    cudaFuncSetAttribute((const void*)g32<64 ,256,2,0,0,1>, cudaFuncAttributeMaxDynamicSharedMemorySize, SM64_256);
    cudaFuncSetAttribute((const void*)g32<512,256,2,1,0,2>, cudaFuncAttributeMaxDynamicSharedMemorySize, SM512_256);
    cudaFuncSetAttribute((const void*)decoder_loop, cudaFuncAttributeMaxDynamicSharedMemorySize, SM_PERS);

    // init state
    cudaMemcpyToSymbolAsync(g_hbuf, h0, 32*512*sizeof(float), 0, cudaMemcpyDeviceToDevice, 0);
    cudaMemcpyToSymbolAsync(g_cbuf, c0, 32*512*sizeof(float), 0, cudaMemcpyDeviceToDevice, 0);

    // precompute: phi_hs, phi_fds, ZX
    g32<512,256,2,0,0,0><<<dim3(2,100),256,SM512_256>>>(Wh, bh, enc, 512, out, 512, 0, lens, nullptr, nullptr);
    g32<64 ,256,2,0,0,1><<<dim3(2,100),256,SM64_256 >>>(Wf, bf, fld, 64 , out, 512, 0, lens, nullptr, nullptr);
    g32<512,256,2,1,0,2><<<dim3(8,65 ),256,SM512_256>>>(lW, lb, emb, 512, out, 2048, 0, lens, nullptr, inp);

    // the whole 65-step recurrence in one persistent kernel
    decoder_loop<<<128, 256, SM_PERS>>>(lW + (size_t)512*2048,
                                        Ws, bs, Wr, br, Wo, bo, oW, ob,
                                        enc, lens, out);

    (void)in_sizes; (void)n_in; (void)out_size;
}

// round 6
// speedup vs baseline: 1.7956x; 1.7956x over previous
#include <cuda_runtime.h>
#include <math.h>

#define SOSID 2
#define EPSF  1e-6f

typedef unsigned long long u64;

// ---------------- persistent device state ----------------
__device__ float g_phi_hs[3200*512];   // tanh(enc @ Wh + bh), rows = b*100+l
__device__ float g_phi_fds[3200*512];  // tanh(field @ Wf + bf)
__device__ float g_zx[2080*2048];      // x_t @ lstm_W[0:512] + lstm_b, rows = t*32+b
__device__ float g_hbuf[2][32*512];
__device__ float g_cbuf[2][32*512];
__device__ float g_ot[32*512];
__device__ float g_gamma[32*512];
__device__ float g_alpha[32*512];
__device__ float g_ctx[32*512];
__device__ float g_att[32*512];
__device__ float g_WsT[512*512];       // WsT[c*512+k] = Ws[k*512+c]
__device__ float g_WrT[512*512];
__device__ float g_WoT[512*1024];      // WoT[c*1024+k] = Wo[k*512+c]
__device__ int          g_cnt;
__device__ volatile int g_gen;

// ---------------- f32x2 helpers ----------------
__device__ __forceinline__ u64 pk2(float lo, float hi){
    u64 r; asm("mov.b64 %0, {%1,%2};" : "=l"(r) : "f"(lo), "f"(hi)); return r;
}
__device__ __forceinline__ void upk2(u64 v, float& lo, float& hi){
    asm("mov.b64 {%0,%1}, %2;" : "=f"(lo), "=f"(hi) : "l"(v));
}
__device__ __forceinline__ u64 ffma2(u64 a, u64 b, u64 c){
    u64 r; asm("fma.rn.f32x2 %0, %1, %2, %3;" : "=l"(r) : "l"(a), "l"(b), "l"(c)); return r;
}
__device__ __forceinline__ u64 fadd2(u64 a, u64 b){
    u64 r; asm("add.rn.f32x2 %0, %1, %2;" : "=l"(r) : "l"(a), "l"(b)); return r;
}
__device__ __forceinline__ float sigf(float x){ return 1.f/(1.f+expf(-x)); }

// ---------------- software grid barrier (148 co-resident blocks) ----------
__device__ __forceinline__ void gsync(){
    __threadfence();
    __syncthreads();
    if (threadIdx.x == 0){
        int g = g_gen;
        if (atomicAdd(&g_cnt, 1) == (int)gridDim.x - 1){
            g_cnt = 0;
            __threadfence();
            g_gen = g + 1;
        } else {
            while (g_gen == g) { __nanosleep(64); }
        }
    }
    __syncthreads();
}

// ================= weight transpose (one-time) =================
__global__ void tr_k(const float* __restrict__ in, int rows, int cols, int which)
{
    __shared__ float tile[32][33];
    float* outp = (which==0) ? g_WsT : (which==1) ? g_WrT : g_WoT;
    int bx = blockIdx.x*32, by = blockIdx.y*32;
    int tx = threadIdx.x & 31, ty = threadIdx.x >> 5;
    #pragma unroll
    for (int j=0;j<4;j++){
        int r = by + ty + j*8, c = bx + tx;
        if (r < rows && c < cols) tile[ty+j*8][tx] = in[(size_t)r*cols + c];
    }
    __syncthreads();
    #pragma unroll
    for (int j=0;j<4;j++){
        int c = bx + ty + j*8, r = by + tx;
        if (r < rows && c < cols) outp[(size_t)c*rows + r] = tile[tx][ty+j*8];
    }
}

// ================= precompute GEMM (passing R3/R4 version) ==================
template<int K, int NT, int KS, int AMODE, int EPI>
__global__ void __launch_bounds__(2*(NT/4)*KS)
g32(const float* __restrict__ W, const float* __restrict__ Bv,
    const float* __restrict__ A, int lda, int ldw,
    const float* __restrict__ p1)
{
    constexpr int CG  = NT/4;
    constexpr int TH  = 2*CG*KS;
    constexpr int ATS = 36;
    extern __shared__ float sm[];
    float* at = sm;
    u64*  red = (u64*)(sm + K*ATS);

    const int tid = threadIdx.x;
    const int cg  = tid % CG;
    const int rh  = (tid / CG) & 1;
    const int ks  = tid / (2*CG);
    const int rowBase = (int)blockIdx.y*32;

    for (int idx = tid; idx < 32*K; idx += TH) {
        int m = idx / K, k = idx - m*K;
        float v;
        if (AMODE==0)      v = A[(size_t)(rowBase+m)*lda + k];
        else               { int tt = blockIdx.y;
                             v = (tt==0) ? A[SOSID*512 + k]
                                         : p1[((size_t)m*64 + (tt-1))*512 + k]; }
        at[k*ATS + m] = v;
    }
    __syncthreads();

    u64 acc[8][4];
    #pragma unroll
    for (int i=0;i<8;i++){ acc[i][0]=0; acc[i][1]=0; acc[i][2]=0; acc[i][3]=0; }

    const int k0 = ks*(K/KS);
    const float* wp = W + (size_t)k0*ldw + (size_t)blockIdx.x*NT + cg*4;
    const float* ap = at + k0*ATS + rh*16;

    #pragma unroll 4
    for (int kk=0; kk<K/KS; kk++) {
        float4 w4 = *(const float4*)wp;
        u64 b0=pk2(w4.x,w4.x), b1=pk2(w4.y,w4.y), b2=pk2(w4.z,w4.z), b3=pk2(w4.w,w4.w);
        wp += ldw;
        u64 aa[8];
        #pragma unroll
        for (int i=0;i<8;i++) aa[i] = ((const u64*)ap)[i];
        ap += ATS;
        #pragma unroll
        for (int m2=0;m2<8;m2++){
            acc[m2][0]=ffma2(aa[m2],b0,acc[m2][0]);
            acc[m2][1]=ffma2(aa[m2],b1,acc[m2][1]);
            acc[m2][2]=ffma2(aa[m2],b2,acc[m2][2]);
            acc[m2][3]=ffma2(aa[m2],b3,acc[m2][3]);
        }
    }

    if (KS>1) {
        u64* mr = red + (size_t)tid*33;
        #pragma unroll
        for (int m2=0;m2<8;m2++){
            mr[4*m2+0]=acc[m2][0]; mr[4*m2+1]=acc[m2][1];
            mr[4*m2+2]=acc[m2][2]; mr[4*m2+3]=acc[m2][3];
        }
        __syncthreads();
        for (int s=KS/2; s>=1; s>>=1){
            if (ks < s){
                const u64* pr = mr + (size_t)(s*2*CG)*33;
                #pragma unroll
                for (int m2=0;m2<8;m2++){
                    acc[m2][0]=fadd2(acc[m2][0],pr[4*m2+0]);
                    acc[m2][1]=fadd2(acc[m2][1],pr[4*m2+1]);
                    acc[m2][2]=fadd2(acc[m2][2],pr[4*m2+2]);
                    acc[m2][3]=fadd2(acc[m2][3],pr[4*m2+3]);
                }
                if (s>1){
                    #pragma unroll
                    for (int m2=0;m2<8;m2++){
                        mr[4*m2+0]=acc[m2][0]; mr[4*m2+1]=acc[m2][1];
                        mr[4*m2+2]=acc[m2][2]; mr[4*m2+3]=acc[m2][3];
                    }
                }
            }
            __syncthreads();
        }
    }
    if (ks) return;

    int c0 = blockIdx.x*NT + cg*4;
    #pragma unroll
    for (int m2=0;m2<8;m2++){
        float v0[4], v1[4];
        upk2(acc[m2][0],v0[0],v1[0]); upk2(acc[m2][1],v0[1],v1[1]);
        upk2(acc[m2][2],v0[2],v1[2]); upk2(acc[m2][3],v0[3],v1[3]);
        #pragma unroll
        for (int r=0;r<2;r++){
            int row = rowBase + rh*16 + 2*m2 + r;
            const float* vv = r ? v1 : v0;
            #pragma unroll
            for (int j=0;j<4;j++){
                int c = c0 + j;
                float x = vv[j] + Bv[c];
                if (EPI==0)      g_phi_hs [(size_t)row*512 +c] = tanhf(x);
                else if (EPI==1) g_phi_fds[(size_t)row*512 +c] = tanhf(x);
                else             g_zx     [(size_t)row*2048+c] = x;
            }
        }
    }
}

// ================= persistent decoder =================
// grid = 148 x 256. Phases separated by software grid sync.

// LSTM on 16 blocks (blk 128..143): 32 h-cols per block, KS=4.
__device__ __forceinline__ void lstm2(
    float* sm, u64* red, const float* __restrict__ lWh,
    const int* __restrict__ lens, int t, int blk, int tid)
{
    const int pb = t & 1, cb = pb ^ 1;
    const int hbase = (blk - 128) * 32;

    for (int idx = tid; idx < 32*512; idx += 256){
        int m = idx >> 9, k = idx & 511;
        sm[k*36 + m] = __ldcg(&g_hbuf[pb][m*512 + k]);
    }
    __syncthreads();

    const int cg = tid & 31;         // h-col (lanes = consecutive cols -> coalesced W)
    const int rh = (tid >> 5) & 1;
    const int ks = tid >> 6;         // 0..3, 128 k each

    u64 acc[8][4];
    #pragma unroll
    for (int i=0;i<8;i++){ acc[i][0]=0; acc[i][1]=0; acc[i][2]=0; acc[i][3]=0; }

    const float* wp = lWh + (size_t)(ks*128)*2048 + hbase + cg;
    const float* ap = sm + (ks*128)*36 + rh*16;
    #pragma unroll 4
    for (int kk=0; kk<128; kk++){
        float w0=wp[0], w1=wp[512], w2=wp[1024], w3=wp[1536];
        u64 b0=pk2(w0,w0), b1=pk2(w1,w1), b2=pk2(w2,w2), b3=pk2(w3,w3);
        wp += 2048;
        u64 aa[8];
        #pragma unroll
        for (int i=0;i<8;i++) aa[i] = ((const u64*)ap)[i];
        ap += 36;
        #pragma unroll
        for (int m2=0;m2<8;m2++){
            acc[m2][0]=ffma2(aa[m2],b0,acc[m2][0]);
            acc[m2][1]=ffma2(aa[m2],b1,acc[m2][1]);
            acc[m2][2]=ffma2(aa[m2],b2,acc[m2][2]);
            acc[m2][3]=ffma2(aa[m2],b3,acc[m2][3]);
        }
    }

    u64* mr = red + (size_t)tid*33;
    #pragma unroll
    for (int m2=0;m2<8;m2++){
        mr[4*m2+0]=acc[m2][0]; mr[4*m2+1]=acc[m2][1];
        mr[4*m2+2]=acc[m2][2]; mr[4*m2+3]=acc[m2][3];
    }
    __syncthreads();
    for (int s=2; s>=1; s>>=1){
        if (ks < s){
            const u64* pr = mr + (size_t)(s*64)*33;
            #pragma unroll
            for (int m2=0;m2<8;m2++){
                acc[m2][0]=fadd2(acc[m2][0],pr[4*m2+0]);
                acc[m2][1]=fadd2(acc[m2][1],pr[4*m2+1]);
                acc[m2][2]=fadd2(acc[m2][2],pr[4*m2+2]);
                acc[m2][3]=fadd2(acc[m2][3],pr[4*m2+3]);
            }
            if (s>1){
                #pragma unroll
                for (int m2=0;m2<8;m2++){
                    mr[4*m2+0]=acc[m2][0]; mr[4*m2+1]=acc[m2][1];
                    mr[4*m2+2]=acc[m2][2]; mr[4*m2+3]=acc[m2][3];
                }
            }
        }
        __syncthreads();
    }

    if (ks == 0){
        const int h = hbase + cg;
        #pragma unroll
        for (int m2=0;m2<8;m2++){
            float zi[2],zj[2],zf[2],zo[2];
            upk2(acc[m2][0],zi[0],zi[1]); upk2(acc[m2][1],zj[0],zj[1]);
            upk2(acc[m2][2],zf[0],zf[1]); upk2(acc[m2][3],zo[0],zo[1]);
            #pragma unroll
            for (int r=0;r<2;r++){
                int b = rh*16 + 2*m2 + r;
                const float* zxp = g_zx + ((size_t)(t*32+b))*2048 + h;
                float vi = zi[r] + zxp[0];
                float vj = zj[r] + zxp[512];
                float vf = zf[r] + zxp[1024];
                float vo = zo[r] + zxp[1536];
                float cp = __ldcg(&g_cbuf[pb][b*512+h]);
                float hp = __ldcg(&g_hbuf[pb][b*512+h]);
                float cn = sigf(vf+1.f)*cp + sigf(vi)*tanhf(vj);
                float hn = sigf(vo)*tanhf(cn);
                bool fin = (t>0) && (t-1 >= lens[b]);
                g_ot[b*512+h]       = fin ? 0.f : hn;
                g_hbuf[cb][b*512+h] = fin ? hp  : hn;
                g_cbuf[cb][b*512+h] = fin ? cp  : cn;
            }
        }
    }
    __syncthreads();
}

__device__ __forceinline__ void logits_part(
    float* sm, u64* red, const float* __restrict__ oW, const float* __restrict__ ob,
    const int* __restrict__ lens, float* __restrict__ out, int tt, int blk, int tid)
{
    for (int idx = tid; idx < 32*512; idx += 256){
        int m = idx >> 9, k = idx & 511;
        sm[k*36 + m] = __ldcg(&g_att[m*512 + k]);
    }
    __syncthreads();

    const int cg = tid & 63;
    const int rh = (tid >> 6) & 1;
    const int ks = tid >> 7;         // 0..1

    u64 acc[8][4];
    #pragma unroll
    for (int i=0;i<8;i++){ acc[i][0]=0; acc[i][1]=0; acc[i][2]=0; acc[i][3]=0; }

    const float* wp = oW + (size_t)(ks*256)*32000 + blk*256 + cg*4;
    const float* ap = sm + (ks*256)*36 + rh*16;
    #pragma unroll 4
    for (int kk=0; kk<256; kk++){
        float4 w4 = *(const float4*)wp;
        u64 b0=pk2(w4.x,w4.x), b1=pk2(w4.y,w4.y), b2=pk2(w4.z,w4.z), b3=pk2(w4.w,w4.w);
        wp += 32000;
        u64 aa[8];
        #pragma unroll
        for (int i=0;i<8;i++) aa[i] = ((const u64*)ap)[i];
        ap += 36;
        #pragma unroll
        for (int m2=0;m2<8;m2++){
            acc[m2][0]=ffma2(aa[m2],b0,acc[m2][0]);
            acc[m2][1]=ffma2(aa[m2],b1,acc[m2][1]);
            acc[m2][2]=ffma2(aa[m2],b2,acc[m2][2]);
            acc[m2][3]=ffma2(aa[m2],b3,acc[m2][3]);
        }
    }

    u64* mr = red + (size_t)tid*33;
    #pragma unroll
    for (int m2=0;m2<8;m2++){
        mr[4*m2+0]=acc[m2][0]; mr[4*m2+1]=acc[m2][1];
        mr[4*m2+2]=acc[m2][2]; mr[4*m2+3]=acc[m2][3];
    }
    __syncthreads();
    if (ks == 0){
        const u64* pr = mr + (size_t)128*33;
        #pragma unroll
        for (int m2=0;m2<8;m2++){
            acc[m2][0]=fadd2(acc[m2][0],pr[4*m2+0]);
            acc[m2][1]=fadd2(acc[m2][1],pr[4*m2+1]);
            acc[m2][2]=fadd2(acc[m2][2],pr[4*m2+2]);
            acc[m2][3]=fadd2(acc[m2][3],pr[4*m2+3]);
        }
        const int c0 = blk*256 + cg*4;
        #pragma unroll
        for (int m2=0;m2<8;m2++){
            float v0[4], v1[4];
            upk2(acc[m2][0],v0[0],v1[0]); upk2(acc[m2][1],v0[1],v1[1]);
            upk2(acc[m2][2],v0[2],v1[2]); upk2(acc[m2][3],v0[3],v1[3]);
            #pragma unroll
            for (int r=0;r<2;r++){
                int row = rh*16 + 2*m2 + r;
                bool fin = (tt>0) && (tt-1 >= lens[row]);
                const float* vv = r ? v1 : v0;
                float* op = out + (size_t)row*2080000 + (size_t)tt*32000 + c0;
                #pragma unroll
                for (int j=0;j<4;j++)
                    op[j] = fin ? 0.f : (vv[j] + ob[c0+j]);
            }
        }
    }
    __syncthreads();
}

__global__ void __launch_bounds__(256, 1)
decoder_loop(const float* __restrict__ lWh,
             const float* __restrict__ bs, const float* __restrict__ br,
             const float* __restrict__ bo,
             const float* __restrict__ oW, const float* __restrict__ ob,
             const float* __restrict__ enc,
             const int* __restrict__ lens,
             float* __restrict__ out)
{
    extern __shared__ float sm[];
    u64* red = (u64*)(sm + 512*36);
    const int blk = blockIdx.x;
    const int tid = threadIdx.x;
    const int warp = tid >> 5, lane = tid & 31;

    for (int t = 0; t < 65; t++){
        // ---------- P1: LSTM(t) on blks 128..143  ||  logits(t-1) on blks 0..124 --
        if (blk >= 128 && blk < 144)
            lstm2(sm, red, lWh, lens, t, blk, tid);
        if (t > 0 && blk < 125)
            logits_part(sm, red, oW, ob, lens, out, t-1, blk, tid);
        gsync();

        // ---------- P2: gamma/alpha — warp per column, smem-staged WT ----------
        if (blk < 128){
            float* at2 = sm;              // ot^T : 512 x 33
            float* wst = sm + 512*33;     // 8 cols x 520
            for (int idx = tid; idx < 32*512; idx += 256){
                int m = idx >> 9, k = idx & 511;
                at2[k*33 + m] = __ldcg(&g_ot[m*512 + k]);
            }
            const float* WT = (blk < 64) ? g_WsT : g_WrT;
            const int c0 = (blk & 63) * 8;
            for (int idx = tid; idx < 8*512; idx += 256){
                int w = idx >> 9, k = idx & 511;
                wst[w*520 + k] = WT[(size_t)(c0+w)*512 + k];
            }
            __syncthreads();
            const int c = c0 + warp;
            const float* a  = at2 + lane;
            const float* wr = wst + warp*520;
            float a0=0.f,a1=0.f,a2=0.f,a3=0.f;
            #pragma unroll 4
            for (int k=0;k<512;k+=4){
                a0 = fmaf(a[(k+0)*33], wr[k+0], a0);
                a1 = fmaf(a[(k+1)*33], wr[k+1], a1);
                a2 = fmaf(a[(k+2)*33], wr[k+2], a2);
                a3 = fmaf(a[(k+3)*33], wr[k+3], a3);
            }
            float s = (a0+a1)+(a2+a3);
            float v = tanhf(s + ((blk<64)? bs[c] : br[c]));
            float* dst = (blk<64)? g_gamma : g_alpha;
            dst[lane*512 + c] = v;
            __syncthreads();
        }
        gsync();

        // ---------- P3: attention per batch (blocks 0..31) ----------
        if (blk < 32){
            const int b = blk;
            float* sg  = sm;          // 512
            float* sa  = sm + 512;    // 512
            float* sh_ = sm + 1024;   // 100
            float* sf_ = sm + 1124;   // 100
            float* sw_ = sm + 1224;   // 100
            float* aux = sm + 1324;   // [0]=sumh,[1]=sumf,[2]=wden

            for (int i = tid; i < 512; i += 256){
                sg[i] = __ldcg(&g_gamma[b*512+i]);
                sa[i] = __ldcg(&g_alpha[b*512+i]);
            }
            __syncthreads();

            for (int l = warp; l < 100; l += 8){
                const float* ph = g_phi_hs  + ((size_t)b*100 + l)*512;
                const float* pf = g_phi_fds + ((size_t)b*100 + l)*512;
                float s1=0.f, s2=0.f;
                for (int k=lane; k<512; k+=32){ s1 += ph[k]*sg[k]; s2 += pf[k]*sa[k]; }
                #pragma unroll
                for (int o=16;o;o>>=1){ s1 += __shfl_xor_sync(~0u,s1,o); s2 += __shfl_xor_sync(~0u,s2,o); }
                if (lane==0){ sh_[l]=s1; sf_[l]=s2; }
            }
            __syncthreads();

            if (warp < 2){
                float* s = warp ? sf_ : sh_;
                float mx = -1e30f;
                for (int l=lane;l<100;l+=32) mx = fmaxf(mx, s[l]);
                #pragma unroll
                for (int o=16;o;o>>=1) mx = fmaxf(mx, __shfl_xor_sync(~0u,mx,o));
                float sum = 0.f;
                for (int l=lane;l<100;l+=32){ float e = expf(s[l]-mx); s[l]=e; sum+=e; }
                #pragma unroll
                for (int o=16;o;o>>=1) sum += __shfl_xor_sync(~0u,sum,o);
                if (lane==0) aux[warp] = EPSF + sum;
            }
            __syncthreads();

            if (warp == 0){
                float d1 = aux[0], d2 = aux[1];
                float wsum = 0.f;
                for (int l=lane;l<100;l+=32){ float w = (sh_[l]/d1)*(sf_[l]/d2); sw_[l]=w; wsum += w; }
                #pragma unroll
                for (int o=16;o;o>>=1) wsum += __shfl_xor_sync(~0u,wsum,o);
                if (lane==0) aux[2] = EPSF + wsum;
            }
            __syncthreads();
            if (warp == 0){ float d = aux[2]; for (int l=lane;l<100;l+=32) sw_[l] = sw_[l]/d; }
            __syncthreads();

            #pragma unroll
            for (int ci=0; ci<2; ci++){
                int h = tid + ci*256;
                float c2 = 0.f;
                const float* e = enc + (size_t)b*100*512 + h;
                #pragma unroll 4
                for (int l=0;l<100;l++) c2 += sw_[l]*e[(size_t)l*512];
                g_ctx[b*512+h] = c2;
            }
        }
        gsync();

        // ---------- P4: att = tanh([ctx|ot] @ Wo + bo) — warp per column -------
        if (blk < 128){
            float* at4 = sm;               // [ctx|ot]^T : 1024 x 33
            float* wst = sm + 1024*33;     // 4 cols x 1040
            for (int idx = tid; idx < 32*1024; idx += 256){
                int m = idx >> 10, k = idx & 1023;
                float v = (k < 512) ? __ldcg(&g_ctx[m*512+k]) : __ldcg(&g_ot[m*512+k-512]);
                at4[k*33 + m] = v;
            }
            const int c0 = blk*4;
            for (int idx = tid; idx < 4*1024; idx += 256){
                int w = idx >> 10, k = idx & 1023;
                wst[w*1040 + k] = g_WoT[(size_t)(c0+w)*1024 + k];
            }
            __syncthreads();
            if (warp < 4){
                const int c = c0 + warp;
                const float* a  = at4 + lane;
                const float* wr = wst + warp*1040;
                float a0=0.f,a1=0.f,a2=0.f,a3=0.f;
                #pragma unroll 4
                for (int k=0;k<1024;k+=4){
                    a0 = fmaf(a[(k+0)*33], wr[k+0], a0);
                    a1 = fmaf(a[(k+1)*33], wr[k+1], a1);
                    a2 = fmaf(a[(k+2)*33], wr[k+2], a2);
                    a3 = fmaf(a[(k+3)*33], wr[k+3], a3);
                }
                float s = (a0+a1)+(a2+a3);
                float v = tanhf(s + bo[c]);
                bool fin = (t>0) && (t-1 >= lens[lane]);
                g_att[lane*512 + c] = fin ? 0.f : v;
            }
            __syncthreads();
        }
        gsync();
    }

    // ---------- tail: logits(64) + final h/c ----------
    if (blk < 125)
        logits_part(sm, red, oW, ob, lens, out, 64, blk, tid);
    if (blk == 125)
        for (int i = tid; i < 16384; i += 256) out[66560000 + i] = __ldcg(&g_hbuf[1][i]);
    if (blk == 126)
        for (int i = tid; i < 16384; i += 256) out[66560000 + 16384 + i] = __ldcg(&g_cbuf[1][i]);
}

// ---------------- host ----------------
extern "C" void kernel_launch(void* const* d_in, const int* in_sizes, int n_in,
                              void* d_out, int out_size)
{
    const float* h0   = (const float*)d_in[0];
    const float* c0   = (const float*)d_in[1];
    const float* inp  = (const float*)d_in[2];   // (32,64,512)
    const float* enc  = (const float*)d_in[3];   // (32,100,512)
    const float* fld  = (const float*)d_in[4];   // (32,100,64)
    const float* emb  = (const float*)d_in[5];   // (32000,512)
    const float* lW   = (const float*)d_in[6];   // (1024,2048)
    const float* lb   = (const float*)d_in[7];
    const float* Wh   = (const float*)d_in[8];
    const float* bh   = (const float*)d_in[9];
    const float* Ws   = (const float*)d_in[10];
    const float* bs   = (const float*)d_in[11];
    const float* Wr   = (const float*)d_in[12];
    const float* br   = (const float*)d_in[13];
    const float* Wf   = (const float*)d_in[14];
    const float* bf   = (const float*)d_in[15];
    const float* Wo   = (const float*)d_in[16];
    const float* bo   = (const float*)d_in[17];
    const float* oW   = (const float*)d_in[18];
    const float* ob   = (const float*)d_in[19];
    const int*   lens = (const int*)  d_in[20];
    float* out = (float*)d_out;

    const int SM512_256 = 512*36*4 + 256*33*8;   // 141312
    const int SM64_256  = 64*36*4  + 256*33*8;
    const int SM_PERS   = 1024*33*4 + 4*1040*4;  // 151808 (P4 is the max)

    cudaFuncSetAttribute((const void*)g32<512,256,2,0,0>, cudaFuncAttributeMaxDynamicSharedMemorySize, SM512_256);
    cudaFuncSetAttribute((const void*)g32<64 ,256,2,0,1>, cudaFuncAttributeMaxDynamicSharedMemorySize, SM64_256);
    cudaFuncSetAttribute((const void*)g32<512,256,2,1,2>, cudaFuncAttributeMaxDynamicSharedMemorySize, SM512_256);
    cudaFuncSetAttribute((const void*)decoder_loop, cudaFuncAttributeMaxDynamicSharedMemorySize, SM_PERS);

    // init state
    cudaMemcpyToSymbolAsync(g_hbuf, h0, 32*512*sizeof(float), 0, cudaMemcpyDeviceToDevice, 0);
    cudaMemcpyToSymbolAsync(g_cbuf, c0, 32*512*sizeof(float), 0, cudaMemcpyDeviceToDevice, 0);

    // one-time weight transposes
    tr_k<<<dim3(16,16),256>>>(Ws, 512, 512, 0);
    tr_k<<<dim3(16,16),256>>>(Wr, 512, 512, 1);
    tr_k<<<dim3(16,32),256>>>(Wo, 1024, 512, 2);

    // precompute: phi_hs, phi_fds, ZX
    g32<512,256,2,0,0><<<dim3(2,100),256,SM512_256>>>(Wh, bh, enc, 512, 512, nullptr);
    g32<64 ,256,2,0,1><<<dim3(2,100),256,SM64_256 >>>(Wf, bf, fld, 64 , 512, nullptr);
    g32<512,256,2,1,2><<<dim3(8,65 ),256,SM512_256>>>(lW, lb, emb, 512, 2048, inp);

    // the whole 65-step recurrence in one persistent kernel (grid = 148 = all SMs)
    decoder_loop<<<148, 256, SM_PERS>>>(lW + (size_t)512*2048,
                                        bs, br, bo, oW, ob,
                                        enc, lens, out);

    (void)in_sizes; (void)n_in; (void)out_size;
}

// round 7
// speedup vs baseline: 2.1616x; 1.2039x over previous
#include <cuda_runtime.h>
#include <math.h>

#define SOSID 2
#define EPSF  1e-6f

typedef unsigned long long u64;

// ---------------- persistent device state ----------------
__device__ float g_phi_hs[3200*512];   // tanh(enc @ Wh + bh), rows = b*100+l
__device__ float g_phi_fds[3200*512];  // tanh(field @ Wf + bf)
__device__ float g_zx[2080*2048];      // x_t @ lstm_W[0:512] + lstm_b, rows = t*32+b
__device__ float g_encT[32*512*104];   // enc transposed: [b][h][l], l padded to 104 w/ zeros
__device__ float g_hbuf[2][32*512];
__device__ float g_cbuf[2][32*512];
__device__ float g_ot[32*512];
__device__ float g_gamma[32*512];
__device__ float g_alpha[32*512];
__device__ float g_ctx[32*512];
__device__ float g_att[32*512];
__device__ float g_WsT[512*512];       // WsT[c*512+k] = Ws[k*512+c]
__device__ float g_WrT[512*512];
__device__ float g_WoT[512*1024];      // WoT[c*1024+k] = Wo[k*512+c]
__device__ int          g_cnt;
__device__ volatile int g_gen;

// ---------------- f32x2 helpers ----------------
__device__ __forceinline__ u64 pk2(float lo, float hi){
    u64 r; asm("mov.b64 %0, {%1,%2};" : "=l"(r) : "f"(lo), "f"(hi)); return r;
}
__device__ __forceinline__ void upk2(u64 v, float& lo, float& hi){
    asm("mov.b64 {%0,%1}, %2;" : "=f"(lo), "=f"(hi) : "l"(v));
}
__device__ __forceinline__ u64 ffma2(u64 a, u64 b, u64 c){
    u64 r; asm("fma.rn.f32x2 %0, %1, %2, %3;" : "=l"(r) : "l"(a), "l"(b), "l"(c)); return r;
}
__device__ __forceinline__ u64 fadd2(u64 a, u64 b){
    u64 r; asm("add.rn.f32x2 %0, %1, %2;" : "=l"(r) : "l"(a), "l"(b)); return r;
}
__device__ __forceinline__ float sigf(float x){ return 1.f/(1.f+expf(-x)); }

// ---------------- pipelined GEMM inner-loop building blocks ----------------
// 4-kk tile: W rows prefetched into registers one tile ahead (hides L2 latency).
__device__ __forceinline__ void load4v(float4 (&w)[4], const float*& wp, int ldw){
    #pragma unroll
    for (int i=0;i<4;i++){ w[i] = *(const float4*)wp; wp += ldw; }
}
__device__ __forceinline__ void comp4v(u64 (&acc)[8][4], const float*& ap, const float4 (&w)[4]){
    #pragma unroll
    for (int i=0;i<4;i++){
        u64 b0=pk2(w[i].x,w[i].x), b1=pk2(w[i].y,w[i].y),
            b2=pk2(w[i].z,w[i].z), b3=pk2(w[i].w,w[i].w);
        u64 aa[8];
        #pragma unroll
        for (int m=0;m<8;m++) aa[m]=((const u64*)ap)[m];
        ap += 36;
        #pragma unroll
        for (int m=0;m<8;m++){
            acc[m][0]=ffma2(aa[m],b0,acc[m][0]);
            acc[m][1]=ffma2(aa[m],b1,acc[m][1]);
            acc[m][2]=ffma2(aa[m],b2,acc[m][2]);
            acc[m][3]=ffma2(aa[m],b3,acc[m][3]);
        }
    }
}
// gated variant: 4 scalars per kk at stride 512 (LSTM gate columns)
__device__ __forceinline__ void load4g(float (&w)[16], const float*& wp){
    #pragma unroll
    for (int i=0;i<4;i++){
        w[i*4+0]=wp[0]; w[i*4+1]=wp[512]; w[i*4+2]=wp[1024]; w[i*4+3]=wp[1536];
        wp += 2048;
    }
}
__device__ __forceinline__ void comp4g(u64 (&acc)[8][4], const float*& ap, const float (&w)[16]){
    #pragma unroll
    for (int i=0;i<4;i++){
        u64 b0=pk2(w[i*4+0],w[i*4+0]), b1=pk2(w[i*4+1],w[i*4+1]),
            b2=pk2(w[i*4+2],w[i*4+2]), b3=pk2(w[i*4+3],w[i*4+3]);
        u64 aa[8];
        #pragma unroll
        for (int m=0;m<8;m++) aa[m]=((const u64*)ap)[m];
        ap += 36;
        #pragma unroll
        for (int m=0;m<8;m++){
            acc[m][0]=ffma2(aa[m],b0,acc[m][0]);
            acc[m][1]=ffma2(aa[m],b1,acc[m][1]);
            acc[m][2]=ffma2(aa[m],b2,acc[m][2]);
            acc[m][3]=ffma2(aa[m],b3,acc[m][3]);
        }
    }
}

// ---------------- software grid barrier (148 co-resident blocks) ----------
__device__ __forceinline__ void gsync(){
    __threadfence();
    __syncthreads();
    if (threadIdx.x == 0){
        int g = g_gen;
        if (atomicAdd(&g_cnt, 1) == (int)gridDim.x - 1){
            g_cnt = 0;
            __threadfence();
            g_gen = g + 1;
        } else {
            while (g_gen == g) { __nanosleep(64); }
        }
    }
    __syncthreads();
}

// ================= one-time weight / enc transposes =================
__global__ void tr_k(const float* __restrict__ in, int rows, int cols, int which)
{
    __shared__ float tile[32][33];
    float* outp = (which==0) ? g_WsT : (which==1) ? g_WrT : g_WoT;
    int bx = blockIdx.x*32, by = blockIdx.y*32;
    int tx = threadIdx.x & 31, ty = threadIdx.x >> 5;
    #pragma unroll
    for (int j=0;j<4;j++){
        int r = by + ty + j*8, c = bx + tx;
        if (r < rows && c < cols) tile[ty+j*8][tx] = in[(size_t)r*cols + c];
    }
    __syncthreads();
    #pragma unroll
    for (int j=0;j<4;j++){
        int c = bx + ty + j*8, r = by + tx;
        if (r < rows && c < cols) outp[(size_t)c*rows + r] = tile[tx][ty+j*8];
    }
}

__global__ void tr_enc(const float* __restrict__ enc)
{
    // enc (32,100,512) -> g_encT (32,512,104), zero-padded in l
    __shared__ float t[32][33];
    int b  = blockIdx.z;
    int l0 = blockIdx.y*32;
    int h0 = blockIdx.x*32;
    int tx = threadIdx.x & 31, ty = threadIdx.x >> 5;  // 256 thr: ty 0..7
    #pragma unroll
    for (int j=0;j<4;j++){
        int l = l0 + ty + j*8;
        t[ty+j*8][tx] = (l < 100) ? enc[((size_t)b*100 + l)*512 + h0 + tx] : 0.f;
    }
    __syncthreads();
    #pragma unroll
    for (int j=0;j<4;j++){
        int h = h0 + ty + j*8;
        int l = l0 + tx;
        if (l < 104) g_encT[((size_t)b*512 + h)*104 + l] = t[tx][ty+j*8];
    }
}

// ================= precompute GEMM (pipelined) ==================
template<int K, int NT, int KS, int AMODE, int EPI>
__global__ void __launch_bounds__(2*(NT/4)*KS)
g32(const float* __restrict__ W, const float* __restrict__ Bv,
    const float* __restrict__ A, int lda, int ldw,
    const float* __restrict__ p1)
{
    constexpr int CG  = NT/4;
    constexpr int TH  = 2*CG*KS;
    constexpr int ATS = 36;
    constexpr int NTILES = (K/KS)/4;
    extern __shared__ float sm[];
    float* at = sm;
    u64*  red = (u64*)(sm + K*ATS);

    const int tid = threadIdx.x;
    const int cg  = tid % CG;
    const int rh  = (tid / CG) & 1;
    const int ks  = tid / (2*CG);
    const int rowBase = (int)blockIdx.y*32;

    for (int idx = tid; idx < 32*K; idx += TH) {
        int m = idx / K, k = idx - m*K;
        float v;
        if (AMODE==0)      v = A[(size_t)(rowBase+m)*lda + k];
        else               { int tt = blockIdx.y;
                             v = (tt==0) ? A[SOSID*512 + k]
                                         : p1[((size_t)m*64 + (tt-1))*512 + k]; }
        at[k*ATS + m] = v;
    }
    __syncthreads();

    u64 acc[8][4];
    #pragma unroll
    for (int i=0;i<8;i++){ acc[i][0]=0; acc[i][1]=0; acc[i][2]=0; acc[i][3]=0; }

    const int k0 = ks*(K/KS);
    const float* wp = W + (size_t)k0*ldw + (size_t)blockIdx.x*NT + cg*4;
    const float* ap = at + k0*ATS + rh*16;

    float4 wa[4], wb[4];
    load4v(wa, wp, ldw);
    #pragma unroll 1
    for (int j=0;j<NTILES/2-1;j++){
        load4v(wb, wp, ldw);
        comp4v(acc, ap, wa);
        load4v(wa, wp, ldw);
        comp4v(acc, ap, wb);
    }
    load4v(wb, wp, ldw);
    comp4v(acc, ap, wa);
    comp4v(acc, ap, wb);

    if (KS>1) {
        u64* mr = red + (size_t)tid*33;
        #pragma unroll
        for (int m2=0;m2<8;m2++){
            mr[4*m2+0]=acc[m2][0]; mr[4*m2+1]=acc[m2][1];
            mr[4*m2+2]=acc[m2][2]; mr[4*m2+3]=acc[m2][3];
        }
        __syncthreads();
        for (int s=KS/2; s>=1; s>>=1){
            if (ks < s){
                const u64* pr = mr + (size_t)(s*2*CG)*33;
                #pragma unroll
                for (int m2=0;m2<8;m2++){
                    acc[m2][0]=fadd2(acc[m2][0],pr[4*m2+0]);
                    acc[m2][1]=fadd2(acc[m2][1],pr[4*m2+1]);
                    acc[m2][2]=fadd2(acc[m2][2],pr[4*m2+2]);
                    acc[m2][3]=fadd2(acc[m2][3],pr[4*m2+3]);
                }
                if (s>1){
                    #pragma unroll
                    for (int m2=0;m2<8;m2++){
                        mr[4*m2+0]=acc[m2][0]; mr[4*m2+1]=acc[m2][1];
                        mr[4*m2+2]=acc[m2][2]; mr[4*m2+3]=acc[m2][3];
                    }
                }
            }
            __syncthreads();
        }
    }
    if (ks) return;

    int c0 = blockIdx.x*NT + cg*4;
    #pragma unroll
    for (int m2=0;m2<8;m2++){
        float v0[4], v1[4];
        upk2(acc[m2][0],v0[0],v1[0]); upk2(acc[m2][1],v0[1],v1[1]);
        upk2(acc[m2][2],v0[2],v1[2]); upk2(acc[m2][3],v0[3],v1[3]);
        #pragma unroll
        for (int r=0;r<2;r++){
            int row = rowBase + rh*16 + 2*m2 + r;
            const float* vv = r ? v1 : v0;
            #pragma unroll
            for (int j=0;j<4;j++){
                int c = c0 + j;
                float x = vv[j] + Bv[c];
                if (EPI==0)      g_phi_hs [(size_t)row*512 +c] = tanhf(x);
                else if (EPI==1) g_phi_fds[(size_t)row*512 +c] = tanhf(x);
                else             g_zx     [(size_t)row*2048+c] = x;
            }
        }
    }
}

// ================= persistent decoder =================
// grid = 148 x 256. Phases separated by software grid sync.

// LSTM on 16 blocks (blk 128..143): 32 h-cols per block, KS=4, pipelined.
__device__ __forceinline__ void lstm2(
    float* sm, u64* red, const float* __restrict__ lWh,
    const int* __restrict__ lens, int t, int blk, int tid)
{
    const int pb = t & 1, cb = pb ^ 1;
    const int hbase = (blk - 128) * 32;

    for (int idx = tid; idx < 32*512; idx += 256){
        int m = idx >> 9, k = idx & 511;
        sm[k*36 + m] = __ldcg(&g_hbuf[pb][m*512 + k]);
    }
    __syncthreads();

    const int cg = tid & 31;
    const int rh = (tid >> 5) & 1;
    const int ks = tid >> 6;         // 0..3, 128 kk each -> 32 tiles

    u64 acc[8][4];
    #pragma unroll
    for (int i=0;i<8;i++){ acc[i][0]=0; acc[i][1]=0; acc[i][2]=0; acc[i][3]=0; }

    const float* wp = lWh + (size_t)(ks*128)*2048 + hbase + cg;
    const float* ap = sm + (ks*128)*36 + rh*16;

    float wa[16], wb[16];
    load4g(wa, wp);
    #pragma unroll 1
    for (int j=0;j<15;j++){
        load4g(wb, wp);
        comp4g(acc, ap, wa);
        load4g(wa, wp);
        comp4g(acc, ap, wb);
    }
    load4g(wb, wp);
    comp4g(acc, ap, wa);
    comp4g(acc, ap, wb);

    u64* mr = red + (size_t)tid*33;
    #pragma unroll
    for (int m2=0;m2<8;m2++){
        mr[4*m2+0]=acc[m2][0]; mr[4*m2+1]=acc[m2][1];
        mr[4*m2+2]=acc[m2][2]; mr[4*m2+3]=acc[m2][3];
    }
    __syncthreads();
    for (int s=2; s>=1; s>>=1){
        if (ks < s){
            const u64* pr = mr + (size_t)(s*64)*33;
            #pragma unroll
            for (int m2=0;m2<8;m2++){
                acc[m2][0]=fadd2(acc[m2][0],pr[4*m2+0]);
                acc[m2][1]=fadd2(acc[m2][1],pr[4*m2+1]);
                acc[m2][2]=fadd2(acc[m2][2],pr[4*m2+2]);
                acc[m2][3]=fadd2(acc[m2][3],pr[4*m2+3]);
            }
            if (s>1){
                #pragma unroll
                for (int m2=0;m2<8;m2++){
                    mr[4*m2+0]=acc[m2][0]; mr[4*m2+1]=acc[m2][1];
                    mr[4*m2+2]=acc[m2][2]; mr[4*m2+3]=acc[m2][3];
                }
            }
        }
        __syncthreads();
    }

    if (ks == 0){
        const int h = hbase + cg;
        #pragma unroll
        for (int m2=0;m2<8;m2++){
            float zi[2],zj[2],zf[2],zo[2];
            upk2(acc[m2][0],zi[0],zi[1]); upk2(acc[m2][1],zj[0],zj[1]);
            upk2(acc[m2][2],zf[0],zf[1]); upk2(acc[m2][3],zo[0],zo[1]);
            #pragma unroll
            for (int r=0;r<2;r++){
                int b = rh*16 + 2*m2 + r;
                const float* zxp = g_zx + ((size_t)(t*32+b))*2048 + h;
                float vi = zi[r] + zxp[0];
                float vj = zj[r] + zxp[512];
                float vf = zf[r] + zxp[1024];
                float vo = zo[r] + zxp[1536];
                float cp = __ldcg(&g_cbuf[pb][b*512+h]);
                float hp = __ldcg(&g_hbuf[pb][b*512+h]);
                float cn = sigf(vf+1.f)*cp + sigf(vi)*tanhf(vj);
                float hn = sigf(vo)*tanhf(cn);
                bool fin = (t>0) && (t-1 >= lens[b]);
                g_ot[b*512+h]       = fin ? 0.f : hn;
                g_hbuf[cb][b*512+h] = fin ? hp  : hn;
                g_cbuf[cb][b*512+h] = fin ? cp  : cn;
            }
        }
    }
    __syncthreads();
}

__device__ __forceinline__ void logits_part(
    float* sm, u64* red, const float* __restrict__ oW, const float* __restrict__ ob,
    const int* __restrict__ lens, float* __restrict__ out, int tt, int blk, int tid)
{
    for (int idx = tid; idx < 32*512; idx += 256){
        int m = idx >> 9, k = idx & 511;
        sm[k*36 + m] = __ldcg(&g_att[m*512 + k]);
    }
    __syncthreads();

    const int cg = tid & 63;
    const int rh = (tid >> 6) & 1;
    const int ks = tid >> 7;         // 0..1, 256 kk each -> 64 tiles

    u64 acc[8][4];
    #pragma unroll
    for (int i=0;i<8;i++){ acc[i][0]=0; acc[i][1]=0; acc[i][2]=0; acc[i][3]=0; }

    const float* wp = oW + (size_t)(ks*256)*32000 + blk*256 + cg*4;
    const float* ap = sm + (ks*256)*36 + rh*16;

    float4 wa[4], wb[4];
    load4v(wa, wp, 32000);
    #pragma unroll 1
    for (int j=0;j<31;j++){
        load4v(wb, wp, 32000);
        comp4v(acc, ap, wa);
        load4v(wa, wp, 32000);
        comp4v(acc, ap, wb);
    }
    load4v(wb, wp, 32000);
    comp4v(acc, ap, wa);
    comp4v(acc, ap, wb);

    u64* mr = red + (size_t)tid*33;
    #pragma unroll
    for (int m2=0;m2<8;m2++){
        mr[4*m2+0]=acc[m2][0]; mr[4*m2+1]=acc[m2][1];
        mr[4*m2+2]=acc[m2][2]; mr[4*m2+3]=acc[m2][3];
    }
    __syncthreads();
    if (ks == 0){
        const u64* pr = mr + (size_t)128*33;
        #pragma unroll
        for (int m2=0;m2<8;m2++){
            acc[m2][0]=fadd2(acc[m2][0],pr[4*m2+0]);
            acc[m2][1]=fadd2(acc[m2][1],pr[4*m2+1]);
            acc[m2][2]=fadd2(acc[m2][2],pr[4*m2+2]);
            acc[m2][3]=fadd2(acc[m2][3],pr[4*m2+3]);
        }
        const int c0 = blk*256 + cg*4;
        #pragma unroll
        for (int m2=0;m2<8;m2++){
            float v0[4], v1[4];
            upk2(acc[m2][0],v0[0],v1[0]); upk2(acc[m2][1],v0[1],v1[1]);
            upk2(acc[m2][2],v0[2],v1[2]); upk2(acc[m2][3],v0[3],v1[3]);
            #pragma unroll
            for (int r=0;r<2;r++){
                int row = rh*16 + 2*m2 + r;
                bool fin = (tt>0) && (tt-1 >= lens[row]);
                const float* vv = r ? v1 : v0;
                float* op = out + (size_t)row*2080000 + (size_t)tt*32000 + c0;
                #pragma unroll
                for (int j=0;j<4;j++)
                    op[j] = fin ? 0.f : (vv[j] + ob[c0+j]);
            }
        }
    }
    __syncthreads();
}

__global__ void __launch_bounds__(256, 1)
decoder_loop(const float* __restrict__ lWh,
             const float* __restrict__ bs, const float* __restrict__ br,
             const float* __restrict__ bo,
             const float* __restrict__ oW, const float* __restrict__ ob,
             const int* __restrict__ lens,
             float* __restrict__ out)
{
    extern __shared__ float sm[];
    u64* red = (u64*)(sm + 512*36);
    const int blk = blockIdx.x;
    const int tid = threadIdx.x;
    const int warp = tid >> 5, lane = tid & 31;

    for (int t = 0; t < 65; t++){
        // ---------- P1: LSTM(t) on blks 128..143  ||  logits(t-1) on blks 0..124 --
        if (blk >= 128 && blk < 144)
            lstm2(sm, red, lWh, lens, t, blk, tid);
        if (t > 0 && blk < 125)
            logits_part(sm, red, oW, ob, lens, out, t-1, blk, tid);
        gsync();

        // ---------- P2: gamma/alpha — warp per column, smem-staged WT ----------
        if (blk < 128){
            float* at2 = sm;              // ot^T : 512 x 33
            float* wst = sm + 512*33;     // 8 cols x 520
            for (int idx = tid; idx < 32*512; idx += 256){
                int m = idx >> 9, k = idx & 511;
                at2[k*33 + m] = __ldcg(&g_ot[m*512 + k]);
            }
            const float* WT = (blk < 64) ? g_WsT : g_WrT;
            const int c0 = (blk & 63) * 8;
            for (int idx = tid; idx < 8*512; idx += 256){
                int w = idx >> 9, k = idx & 511;
                wst[w*520 + k] = WT[(size_t)(c0+w)*512 + k];
            }
            __syncthreads();
            const int c = c0 + warp;
            const float* a  = at2 + lane;
            const float* wr = wst + warp*520;
            float a0=0.f,a1=0.f,a2=0.f,a3=0.f;
            #pragma unroll 4
            for (int k=0;k<512;k+=4){
                a0 = fmaf(a[(k+0)*33], wr[k+0], a0);
                a1 = fmaf(a[(k+1)*33], wr[k+1], a1);
                a2 = fmaf(a[(k+2)*33], wr[k+2], a2);
                a3 = fmaf(a[(k+3)*33], wr[k+3], a3);
            }
            float s = (a0+a1)+(a2+a3);
            float v = tanhf(s + ((blk<64)? bs[c] : br[c]));
            float* dst = (blk<64)? g_gamma : g_alpha;
            dst[lane*512 + c] = v;
            __syncthreads();
        }
        gsync();

        // ---------- P3: attention per batch (blocks 0..31) ----------
        if (blk < 32){
            const int b = blk;
            float* sg  = sm;          // 512
            float* sa  = sm + 512;    // 512
            float* sh_ = sm + 1024;   // 100
            float* sf_ = sm + 1124;   // 100
            float* sw_ = sm + 1224;   // 104 (padded)
            float* aux = sm + 1328;   // [0]=sumh,[1]=sumf,[2]=wden

            for (int i = tid; i < 512; i += 256){
                sg[i] = __ldcg(&g_gamma[b*512+i]);
                sa[i] = __ldcg(&g_alpha[b*512+i]);
            }
            __syncthreads();

            for (int l = warp; l < 100; l += 8){
                const float* ph = g_phi_hs  + ((size_t)b*100 + l)*512;
                const float* pf = g_phi_fds + ((size_t)b*100 + l)*512;
                float s1=0.f, s2=0.f;
                for (int k=lane; k<512; k+=32){ s1 += ph[k]*sg[k]; s2 += pf[k]*sa[k]; }
                #pragma unroll
                for (int o=16;o;o>>=1){ s1 += __shfl_xor_sync(~0u,s1,o); s2 += __shfl_xor_sync(~0u,s2,o); }
                if (lane==0){ sh_[l]=s1; sf_[l]=s2; }
            }
            __syncthreads();

            if (warp < 2){
                float* s = warp ? sf_ : sh_;
                float mx = -1e30f;
                for (int l=lane;l<100;l+=32) mx = fmaxf(mx, s[l]);
                #pragma unroll
                for (int o=16;o;o>>=1) mx = fmaxf(mx, __shfl_xor_sync(~0u,mx,o));
                float sum = 0.f;
                for (int l=lane;l<100;l+=32){ float e = expf(s[l]-mx); s[l]=e; sum+=e; }
                #pragma unroll
                for (int o=16;o;o>>=1) sum += __shfl_xor_sync(~0u,sum,o);
                if (lane==0) aux[warp] = EPSF + sum;
            }
            __syncthreads();

            if (warp == 0){
                float d1 = aux[0], d2 = aux[1];
                float wsum = 0.f;
                for (int l=lane;l<100;l+=32){ float w = (sh_[l]/d1)*(sf_[l]/d2); sw_[l]=w; wsum += w; }
                #pragma unroll
                for (int o=16;o;o>>=1) wsum += __shfl_xor_sync(~0u,wsum,o);
                if (lane==0) aux[2] = EPSF + wsum;
            }
            __syncthreads();
            if (warp == 0){
                float d = aux[2];
                for (int l=lane;l<100;l+=32) sw_[l] = sw_[l]/d;
                if (lane < 4) sw_[100+lane] = 0.f;
            }
            __syncthreads();

            #pragma unroll
            for (int ci=0; ci<2; ci++){
                int h = tid + ci*256;
                const float4* e = (const float4*)(g_encT + ((size_t)b*512 + h)*104);
                float c2 = 0.f;
                #pragma unroll
                for (int l4=0; l4<26; l4++){
                    float4 ev = e[l4];
                    int l = l4*4;
                    c2 += sw_[l+0]*ev.x + sw_[l+1]*ev.y + sw_[l+2]*ev.z + sw_[l+3]*ev.w;
                }
                g_ctx[b*512+h] = c2;
            }
        }
        gsync();

        // ---------- P4: att = tanh([ctx|ot] @ Wo + bo), 64 blocks x 8 warp-cols --
        if (blk < 64){
            float* at4 = sm;               // [ctx|ot]^T : 1024 x 33
            float* wst = sm + 1024*33;     // 8 cols x 1040
            for (int idx = tid; idx < 32*1024; idx += 256){
                int m = idx >> 10, k = idx & 1023;
                float v = (k < 512) ? __ldcg(&g_ctx[m*512+k]) : __ldcg(&g_ot[m*512+k-512]);
                at4[k*33 + m] = v;
            }
            const int c0 = blk*8;
            for (int idx = tid; idx < 8*1024; idx += 256){
                int w = idx >> 10, k = idx & 1023;
                wst[w*1040 + k] = g_WoT[(size_t)(c0+w)*1024 + k];
            }
            __syncthreads();
            const int c = c0 + warp;
            const float* a  = at4 + lane;
            const float* wr = wst + warp*1040;
            float a0=0.f,a1=0.f,a2=0.f,a3=0.f;
            #pragma unroll 4
            for (int k=0;k<1024;k+=4){
                a0 = fmaf(a[(k+0)*33], wr[k+0], a0);
                a1 = fmaf(a[(k+1)*33], wr[k+1], a1);
                a2 = fmaf(a[(k+2)*33], wr[k+2], a2);
                a3 = fmaf(a[(k+3)*33], wr[k+3], a3);
            }
            float s = (a0+a1)+(a2+a3);
            float v = tanhf(s + bo[c]);
            bool fin = (t>0) && (t-1 >= lens[lane]);
            g_att[lane*512 + c] = fin ? 0.f : v;
            __syncthreads();
        }
        gsync();
    }

    // ---------- tail: logits(64) + final h/c ----------
    if (blk < 125)
        logits_part(sm, red, oW, ob, lens, out, 64, blk, tid);
    if (blk == 125)
        for (int i = tid; i < 16384; i += 256) out[66560000 + i] = __ldcg(&g_hbuf[1][i]);
    if (blk == 126)
        for (int i = tid; i < 16384; i += 256) out[66560000 + 16384 + i] = __ldcg(&g_cbuf[1][i]);
}

// ---------------- host ----------------
extern "C" void kernel_launch(void* const* d_in, const int* in_sizes, int n_in,
                              void* d_out, int out_size)
{
    const float* h0   = (const float*)d_in[0];
    const float* c0   = (const float*)d_in[1];
    const float* inp  = (const float*)d_in[2];   // (32,64,512)
    const float* enc  = (const float*)d_in[3];   // (32,100,512)
    const float* fld  = (const float*)d_in[4];   // (32,100,64)
    const float* emb  = (const float*)d_in[5];   // (32000,512)
    const float* lW   = (const float*)d_in[6];   // (1024,2048)
    const float* lb   = (const float*)d_in[7];
    const float* Wh   = (const float*)d_in[8];
    const float* bh   = (const float*)d_in[9];
    const float* Ws   = (const float*)d_in[10];
    const float* bs   = (const float*)d_in[11];
    const float* Wr   = (const float*)d_in[12];
    const float* br   = (const float*)d_in[13];
    const float* Wf   = (const float*)d_in[14];
    const float* bf   = (const float*)d_in[15];
    const float* Wo   = (const float*)d_in[16];
    const float* bo   = (const float*)d_in[17];
    const float* oW   = (const float*)d_in[18];
    const float* ob   = (const float*)d_in[19];
    const int*   lens = (const int*)  d_in[20];
    float* out = (float*)d_out;

    const int SM512_256 = 512*36*4 + 256*33*8;   // 141312
    const int SM64_256  = 64*36*4  + 256*33*8;
    const int SM_PERS   = 1024*33*4 + 8*1040*4;  // 168448 (P4 is the max)

    cudaFuncSetAttribute((const void*)g32<512,256,2,0,0>, cudaFuncAttributeMaxDynamicSharedMemorySize, SM512_256);
    cudaFuncSetAttribute((const void*)g32<64 ,256,2,0,1>, cudaFuncAttributeMaxDynamicSharedMemorySize, SM64_256);
    cudaFuncSetAttribute((const void*)g32<512,256,2,1,2>, cudaFuncAttributeMaxDynamicSharedMemorySize, SM512_256);
    cudaFuncSetAttribute((const void*)decoder_loop, cudaFuncAttributeMaxDynamicSharedMemorySize, SM_PERS);

    // init state
    cudaMemcpyToSymbolAsync(g_hbuf, h0, 32*512*sizeof(float), 0, cudaMemcpyDeviceToDevice, 0);
    cudaMemcpyToSymbolAsync(g_cbuf, c0, 32*512*sizeof(float), 0, cudaMemcpyDeviceToDevice, 0);

    // one-time transposes
    tr_k<<<dim3(16,16),256>>>(Ws, 512, 512, 0);
    tr_k<<<dim3(16,16),256>>>(Wr, 512, 512, 1);
    tr_k<<<dim3(16,32),256>>>(Wo, 1024, 512, 2);
    tr_enc<<<dim3(16,4,32),256>>>(enc);

    // precompute: phi_hs, phi_fds, ZX
    g32<512,256,2,0,0><<<dim3(2,100),256,SM512_256>>>(Wh, bh, enc, 512, 512, nullptr);
    g32<64 ,256,2,0,1><<<dim3(2,100),256,SM64_256 >>>(Wf, bf, fld, 64 , 512, nullptr);
    g32<512,256,2,1,2><<<dim3(8,65 ),256,SM512_256>>>(lW, lb, emb, 512, 2048, inp);

    // the whole 65-step recurrence in one persistent kernel (grid = 148 = all SMs)
    decoder_loop<<<148, 256, SM_PERS>>>(lW + (size_t)512*2048,
                                        bs, br, bo, oW, ob,
                                        lens, out);

    (void)in_sizes; (void)n_in; (void)out_size;
}